// round 5
// baseline (speedup 1.0000x reference)
#include <cuda_runtime.h>
#include <cuda_bf16.h>
#include <cstdint>

// Problem constants
#define B_  64
#define S_  2048
#define E_  256
#define H_  256

#define NCONS 64          // consumer CTAs (one per batch)
#define NPROD 84          // producer CTAs
#define NCTAS (NCONS + NPROD)

typedef unsigned long long u64t;

// Scratch (device-global: runtime allocation is forbidden)
__device__ float  g_xw[(size_t)B_ * S_ * H_];  // 128 MB: xw[b,s,h]
__device__ float2 g_Uw2[(H_ / 2) * H_];        // g_Uw2[j][h] = (Uw[h][2j], Uw[h][2j+1])
__device__ float  g_WwT[E_ * H_];              // WwT[e][h] = Ww[h][e]
__device__ int    g_flag[S_];                  // per-timestep ready flags

// ---------------------------------------------------------------------------
// Helpers: packed f32x2 + memory ordering
// ---------------------------------------------------------------------------
__device__ __forceinline__ u64t ffma2(u64t a, u64t b, u64t c) {
    u64t d;
    asm("fma.rn.f32x2 %0, %1, %2, %3;" : "=l"(d) : "l"(a), "l"(b), "l"(c));
    return d;
}
__device__ __forceinline__ u64t dup2(float v) {
    u64t d;
    asm("mov.b64 %0, {%1, %1};" : "=l"(d) : "f"(v));
    return d;
}
__device__ __forceinline__ float2 unpack2(u64t p) {
    float2 r;
    asm("mov.b64 {%0, %1}, %2;" : "=f"(r.x), "=f"(r.y) : "l"(p));
    return r;
}
__device__ __forceinline__ u64t as_u64(double d) { return __double_as_longlong(d); }

__device__ __forceinline__ int ld_acquire_gpu(const int* p) {
    int v;
    asm volatile("ld.acquire.gpu.global.b32 %0, [%1];" : "=r"(v) : "l"(p) : "memory");
    return v;
}
__device__ __forceinline__ void st_release_gpu(int* p, int v) {
    asm volatile("st.release.gpu.global.b32 [%0], %1;" :: "l"(p), "r"(v) : "memory");
}
__device__ __forceinline__ float ld_cg_f(const float* p) {
    float v;
    asm volatile("ld.global.cg.f32 %0, [%1];" : "=f"(v) : "l"(p) : "memory");
    return v;
}

// ---------------------------------------------------------------------------
// prep: build WwT and packed Uw pairs, zero flags
// ---------------------------------------------------------------------------
__global__ void prep(const float* __restrict__ Uw, const float* __restrict__ Ww) {
    int k = blockIdx.x;       // 0..255
    int h = threadIdx.x;      // 0..255
    g_WwT[k * H_ + h] = Ww[h * E_ + k];
    float u = Uw[h * H_ + k];
    if (k & 1) g_Uw2[(k >> 1) * H_ + h].y = u;
    else       g_Uw2[(k >> 1) * H_ + h].x = u;
    if (k < 8) g_flag[k * H_ + h] = 0;   // 8*256 = 2048 flags
}

// ---------------------------------------------------------------------------
// Fused persistent kernel: 64 consumers + 84 producers, all co-resident.
// ---------------------------------------------------------------------------
#define PREG 88                       // packed Uw pair-rows in registers
#define PSM  (H_ / 2 - PREG)          // 40 pair-rows in smem

// smem: [ su: PSM*H_ u64t ][ v: 2*H_ float ]
#define SMEM_BYTES (PSM * H_ * 8 + 2 * H_ * 4)

#define PK 16
#define APAD 4
#define BPAD 4

__global__ __launch_bounds__(256, 1)
void fused(const float* __restrict__ x,       // [B,S,E]
           const float* __restrict__ Wb,      // [H]
           const float* __restrict__ Ub,      // [H]
           float* __restrict__ Out,           // [B,S,H]
           float* __restrict__ Tfin) {        // [B,H]
    extern __shared__ float sm[];
    const int tid = threadIdx.x;

    if (blockIdx.x >= NCONS) {
        // ================= PRODUCER: one 64x256x256 GEMM per timestep =====
        const int p  = blockIdx.x - NCONS;
        float* As = sm;                                   // [PK][64+APAD]
        float* Bs = sm + PK * (64 + APAD);                // [PK][256+BPAD]
        const int ASTR = 64 + APAD;
        const int BSTR = H_ + BPAD;

        const int tx = tid & 15;                           // h quad group
        const int ty = tid >> 4;                           // b quad group
        const int arow = tid >> 2, akq = tid & 3;          // A-tile loads
        const int bk = tid >> 4, bh0 = (tid & 15) * 16;    // B-tile loads

        // per-thread bias (4 quads at h = tx*4 + 64q)
        float4 bias[4];
        #pragma unroll
        for (int q = 0; q < 4; q++)
            bias[q] = *(const float4*)&Wb[tx * 4 + 64 * q];

        for (int s = p; s < S_; s += NPROD) {
            u64t acc[4][8];                    // [b-row][packed h pair]
            #pragma unroll
            for (int r = 0; r < 4; r++)
                #pragma unroll
                for (int c = 0; c < 8; c++) acc[r][c] = 0ull;

            const float* xs = x + (size_t)s * E_;
            float4 ra  = *(const float4*)&xs[(size_t)arow * S_ * E_ + akq * 4];
            float4 rb0 = *(const float4*)&g_WwT[bk * H_ + bh0 + 0];
            float4 rb1 = *(const float4*)&g_WwT[bk * H_ + bh0 + 4];
            float4 rb2 = *(const float4*)&g_WwT[bk * H_ + bh0 + 8];
            float4 rb3 = *(const float4*)&g_WwT[bk * H_ + bh0 + 12];

            for (int k0 = 0; k0 < E_; k0 += PK) {
                As[(akq * 4 + 0) * ASTR + arow] = ra.x;
                As[(akq * 4 + 1) * ASTR + arow] = ra.y;
                As[(akq * 4 + 2) * ASTR + arow] = ra.z;
                As[(akq * 4 + 3) * ASTR + arow] = ra.w;
                *(float4*)&Bs[bk * BSTR + bh0 + 0]  = rb0;
                *(float4*)&Bs[bk * BSTR + bh0 + 4]  = rb1;
                *(float4*)&Bs[bk * BSTR + bh0 + 8]  = rb2;
                *(float4*)&Bs[bk * BSTR + bh0 + 12] = rb3;
                __syncthreads();

                if (k0 + PK < E_) {
                    const int kn = k0 + PK;
                    ra  = *(const float4*)&xs[(size_t)arow * S_ * E_ + kn + akq * 4];
                    rb0 = *(const float4*)&g_WwT[(kn + bk) * H_ + bh0 + 0];
                    rb1 = *(const float4*)&g_WwT[(kn + bk) * H_ + bh0 + 4];
                    rb2 = *(const float4*)&g_WwT[(kn + bk) * H_ + bh0 + 8];
                    rb3 = *(const float4*)&g_WwT[(kn + bk) * H_ + bh0 + 12];
                }

                #pragma unroll
                for (int k = 0; k < PK; k++) {
                    float4  a  = *(const float4*)&As[k * ASTR + ty * 4];
                    double2 b0 = *(const double2*)&Bs[k * BSTR + tx * 4 + 0];
                    double2 b1 = *(const double2*)&Bs[k * BSTR + tx * 4 + 64];
                    double2 b2 = *(const double2*)&Bs[k * BSTR + tx * 4 + 128];
                    double2 b3 = *(const double2*)&Bs[k * BSTR + tx * 4 + 192];
                    u64t p0 = as_u64(b0.x), p1 = as_u64(b0.y);
                    u64t p2 = as_u64(b1.x), p3 = as_u64(b1.y);
                    u64t p4 = as_u64(b2.x), p5 = as_u64(b2.y);
                    u64t p6 = as_u64(b3.x), p7 = as_u64(b3.y);
                    #pragma unroll
                    for (int r = 0; r < 4; r++) {
                        float av = (r == 0) ? a.x : (r == 1) ? a.y : (r == 2) ? a.z : a.w;
                        u64t aa = dup2(av);
                        acc[r][0] = ffma2(aa, p0, acc[r][0]);
                        acc[r][1] = ffma2(aa, p1, acc[r][1]);
                        acc[r][2] = ffma2(aa, p2, acc[r][2]);
                        acc[r][3] = ffma2(aa, p3, acc[r][3]);
                        acc[r][4] = ffma2(aa, p4, acc[r][4]);
                        acc[r][5] = ffma2(aa, p5, acc[r][5]);
                        acc[r][6] = ffma2(aa, p6, acc[r][6]);
                        acc[r][7] = ffma2(aa, p7, acc[r][7]);
                    }
                }
                __syncthreads();
            }

            // epilogue: xw[b,s,h] = acc + Wb[h]
            #pragma unroll
            for (int r = 0; r < 4; r++) {
                const int b = ty * 4 + r;
                float* row = g_xw + ((size_t)b * S_ + s) * H_;
                #pragma unroll
                for (int q = 0; q < 4; q++) {
                    float2 e0 = unpack2(acc[r][q * 2 + 0]);
                    float2 e1 = unpack2(acc[r][q * 2 + 1]);
                    float4 o = make_float4(e0.x + bias[q].x, e0.y + bias[q].y,
                                           e1.x + bias[q].z, e1.y + bias[q].w);
                    *(float4*)&row[tx * 4 + 64 * q] = o;
                }
            }
            __syncthreads();
            if (tid == 0) {
                __threadfence();
                st_release_gpu(&g_flag[s], 1);
            }
        }
        return;
    }

    // ================= CONSUMER (per-batch recurrence) =====================
    u64t*  su  = (u64t*)sm;                       // PSM pair-rows x H_
    float* vsm = sm + PSM * H_ * 2;               // 2 x H_ double buffer

    const int b = blockIdx.x;

    // Register-cache packed pairs 0..PREG-1:  uw2[j] = (Uw[tid][2j], Uw[tid][2j+1])
    u64t uw2[PREG];
    const u64t* Uw2u = (const u64t*)g_Uw2;
    #pragma unroll
    for (int j = 0; j < PREG; j++)
        uw2[j] = Uw2u[j * H_ + tid];

    // smem pairs PREG..127
    for (int r = 0; r < PSM; r++)
        su[r * H_ + tid] = Uw2u[(PREG + r) * H_ + tid];
    __syncthreads();

    const float ub = Ub[tid];
    float t = 0.0f;

    const float* xwp = g_xw + (size_t)b * S_ * H_ + tid;
    float*       op  = Out  + (size_t)b * S_ * H_ + tid;

    while (ld_acquire_gpu(&g_flag[0]) == 0) { }
    float xv = __ldcs(xwp);

    for (int s = 0; s < S_; s++) {
        float v = tanhf(xv + t);
        float* vb = vsm + (s & 1) * H_;
        vb[tid] = v;
        __syncthreads();

        // Speculative next-step fetch: acquire flag + load xw; validate AFTER dot.
        int   fspec = 1;
        float xn    = 0.0f;
        const float* xnp = xwp + (size_t)(s + 1) * H_;
        if (s + 1 < S_) {
            fspec = ld_acquire_gpu(&g_flag[s + 1]);
            xn    = __ldcs(xnp);
        }

        const double2* vq = (const double2*)vb;   // 64 entries = 128 pairs
        u64t a0 = 0, a1 = 0, a2 = 0, a3 = 0, a4 = 0, a5 = 0, a6 = 0, a7 = 0;

        double2 c0 = vq[0];
        double2 c1 = vq[1];

        // Register section: pairs [0, PREG) = 22 groups of 4 pairs
        #pragma unroll
        for (int g = 0; g < PREG / 4; g++) {
            double2 n0 = vq[2 * g + 2];
            double2 n1 = vq[2 * g + 3];
            const int j = 4 * g;
            a0 = ffma2(uw2[j + 0], as_u64(c0.x), a0);
            a1 = ffma2(uw2[j + 1], as_u64(c0.y), a1);
            a2 = ffma2(uw2[j + 2], as_u64(c1.x), a2);
            a3 = ffma2(uw2[j + 3], as_u64(c1.y), a3);
            c0 = n0; c1 = n1;
        }

        // Shared section: pairs [PREG, 128) = 10 groups of 4 pairs
        const u64t* sup = su + tid;
        #pragma unroll
        for (int g = PREG / 4; g < 32; g++) {
            double2 n0, n1;
            if (g + 1 < 32) { n0 = vq[2 * g + 2]; n1 = vq[2 * g + 3]; }
            else            { n0 = c0;            n1 = c1;            }
            const int r = 4 * g - PREG;
            u64t u0 = sup[(r + 0) * H_];
            u64t u1 = sup[(r + 1) * H_];
            u64t u2 = sup[(r + 2) * H_];
            u64t u3 = sup[(r + 3) * H_];
            a4 = ffma2(u0, as_u64(c0.x), a4);
            a5 = ffma2(u1, as_u64(c0.y), a5);
            a6 = ffma2(u2, as_u64(c1.x), a6);
            a7 = ffma2(u3, as_u64(c1.y), a7);
            c0 = n0; c1 = n1;
        }

        float2 e0 = unpack2(a0), e1 = unpack2(a1), e2 = unpack2(a2), e3 = unpack2(a3);
        float2 e4 = unpack2(a4), e5 = unpack2(a5), e6 = unpack2(a6), e7 = unpack2(a7);
        t = ub + (((e0.x + e0.y) + (e1.x + e1.y)) + ((e2.x + e2.y) + (e3.x + e3.y)))
               + (((e4.x + e4.y) + (e5.x + e5.y)) + ((e6.x + e6.y) + (e7.x + e7.y)));

        __stcs(&op[(size_t)s * H_], t);

        // Validate speculation (rare slow path after initial ramp)
        if (s + 1 < S_) {
            if (fspec == 0) {
                while (ld_acquire_gpu(&g_flag[s + 1]) == 0) { }
                xn = ld_cg_f(xnp);
            }
            xv = xn;
        }
    }

    Tfin[b * H_ + tid] = t;
}

// ---------------------------------------------------------------------------
// Launcher
// ---------------------------------------------------------------------------
extern "C" void kernel_launch(void* const* d_in, const int* in_sizes, int n_in,
                              void* d_out, int out_size) {
    const float* x  = (const float*)d_in[0];   // [B,S,E]
    const float* Ww = (const float*)d_in[1];   // [H,E]
    const float* Wb = (const float*)d_in[2];   // [H]
    const float* Uw = (const float*)d_in[3];   // [H,H]
    const float* Ub = (const float*)d_in[4];   // [H]

    float* out  = (float*)d_out;
    float* tfin = out;                          // [B,H]
    float* O    = out + (size_t)B_ * H_;        // [B,S,H]

    cudaFuncSetAttribute(fused, cudaFuncAttributeMaxDynamicSharedMemorySize,
                         SMEM_BYTES);

    prep<<<H_, H_>>>(Uw, Ww);
    fused<<<NCTAS, 256, SMEM_BYTES>>>(x, Wb, Ub, O, tfin);
}

// round 6
// speedup vs baseline: 1.1346x; 1.1346x over previous
#include <cuda_runtime.h>
#include <cuda_bf16.h>
#include <cstdint>

// Problem constants
#define B_  64
#define S_  2048
#define E_  256
#define H_  256

#define NCONS 64          // consumer CTAs (one per batch)
#define NPROD 84          // producer CTAs
#define NCTAS (NCONS + NPROD)

// Scratch (device-global: runtime allocation is forbidden)
__device__ float g_xw[(size_t)B_ * S_ * H_];   // 128 MB: xw[b,s,h]
__device__ float g_UwT[H_ * H_];               // UwT[k][h] = Uw[h][k]
__device__ float g_WwT[E_ * H_];               // WwT[e][h] = Ww[h][e]
__device__ int   g_flag[S_];                   // per-timestep ready flags

__device__ __forceinline__ int ld_acquire_gpu(const int* p) {
    int v;
    asm volatile("ld.acquire.gpu.global.b32 %0, [%1];" : "=r"(v) : "l"(p) : "memory");
    return v;
}
__device__ __forceinline__ void st_release_gpu(int* p, int v) {
    asm volatile("st.release.gpu.global.b32 [%0], %1;" :: "l"(p), "r"(v) : "memory");
}
__device__ __forceinline__ float ld_cg_f(const float* p) {
    float v;
    asm volatile("ld.global.cg.f32 %0, [%1];" : "=f"(v) : "l"(p) : "memory");
    return v;
}

// Fast tanh: 1 - 2/(e^{2x}+1). ~6 instrs (2 MUFU). |err| ~1e-6; exact
// saturation at +/-inf (e^inf -> inf -> rcp -> 0; e^-inf -> 0 -> 1-2 = -1).
__device__ __forceinline__ float fast_tanh(float x) {
    float e = __expf(2.0f * x);
    float r;
    asm("rcp.approx.f32 %0, %1;" : "=f"(r) : "f"(e + 1.0f));
    return fmaf(-2.0f, r, 1.0f);
}

// ---------------------------------------------------------------------------
// prep: transpose Uw and Ww, zero flags
// ---------------------------------------------------------------------------
__global__ void prep(const float* __restrict__ Uw, const float* __restrict__ Ww) {
    int k = blockIdx.x;
    int h = threadIdx.x;
    g_UwT[k * H_ + h] = Uw[h * H_ + k];
    g_WwT[k * H_ + h] = Ww[h * E_ + k];
    if (k < 8) g_flag[k * H_ + h] = 0;   // 8*256 = 2048 flags
}

// ---------------------------------------------------------------------------
// Fused persistent kernel: 64 consumers + 84 producers, all co-resident.
// ---------------------------------------------------------------------------
#define UREG 192
#define USM  (H_ - UREG)

#define SCAN_SMEM_FLOATS (USM * H_ + 2 * H_)
#define SMEM_BYTES (SCAN_SMEM_FLOATS * 4)

#define PK 16
#define APAD 4
#define BPAD 4

__global__ __launch_bounds__(256, 1)
void fused(const float* __restrict__ x,       // [B,S,E]
           const float* __restrict__ Wb,      // [H]
           const float* __restrict__ Ub,      // [H]
           float* __restrict__ Out,           // [B,S,H]
           float* __restrict__ Tfin) {        // [B,H]
    extern __shared__ float sm[];
    const int tid = threadIdx.x;

    if (blockIdx.x >= NCONS) {
        // ================= PRODUCER: one 64x256x256 GEMM per timestep =====
        const int p  = blockIdx.x - NCONS;
        float* As = sm;                                   // [PK][64+APAD]
        float* Bs = sm + PK * (64 + APAD);                // [PK][256+BPAD]
        const int ASTR = 64 + APAD;
        const int BSTR = H_ + BPAD;

        const int tx = tid & 15;                           // h quad group
        const int ty = tid >> 4;                           // b quad group
        const int arow = tid >> 2, akq = tid & 3;          // A-tile loads
        const int bk = tid >> 4, bh0 = (tid & 15) * 16;    // B-tile loads

        float4 bias[4];
        #pragma unroll
        for (int q = 0; q < 4; q++)
            bias[q] = *(const float4*)&Wb[tx * 4 + 64 * q];

        for (int s = p; s < S_; s += NPROD) {
            float acc[4][16] = {};

            const float* xs = x + (size_t)s * E_;
            float4 ra  = *(const float4*)&xs[(size_t)arow * S_ * E_ + akq * 4];
            float4 rb0 = *(const float4*)&g_WwT[bk * H_ + bh0 + 0];
            float4 rb1 = *(const float4*)&g_WwT[bk * H_ + bh0 + 4];
            float4 rb2 = *(const float4*)&g_WwT[bk * H_ + bh0 + 8];
            float4 rb3 = *(const float4*)&g_WwT[bk * H_ + bh0 + 12];

            for (int k0 = 0; k0 < E_; k0 += PK) {
                As[(akq * 4 + 0) * ASTR + arow] = ra.x;
                As[(akq * 4 + 1) * ASTR + arow] = ra.y;
                As[(akq * 4 + 2) * ASTR + arow] = ra.z;
                As[(akq * 4 + 3) * ASTR + arow] = ra.w;
                *(float4*)&Bs[bk * BSTR + bh0 + 0]  = rb0;
                *(float4*)&Bs[bk * BSTR + bh0 + 4]  = rb1;
                *(float4*)&Bs[bk * BSTR + bh0 + 8]  = rb2;
                *(float4*)&Bs[bk * BSTR + bh0 + 12] = rb3;
                __syncthreads();

                if (k0 + PK < E_) {
                    const int kn = k0 + PK;
                    ra  = *(const float4*)&xs[(size_t)arow * S_ * E_ + kn + akq * 4];
                    rb0 = *(const float4*)&g_WwT[(kn + bk) * H_ + bh0 + 0];
                    rb1 = *(const float4*)&g_WwT[(kn + bk) * H_ + bh0 + 4];
                    rb2 = *(const float4*)&g_WwT[(kn + bk) * H_ + bh0 + 8];
                    rb3 = *(const float4*)&g_WwT[(kn + bk) * H_ + bh0 + 12];
                }

                #pragma unroll
                for (int k = 0; k < PK; k++) {
                    float4 a  = *(const float4*)&As[k * ASTR + ty * 4];
                    float4 b0 = *(const float4*)&Bs[k * BSTR + tx * 4 + 0];
                    float4 b1 = *(const float4*)&Bs[k * BSTR + tx * 4 + 64];
                    float4 b2 = *(const float4*)&Bs[k * BSTR + tx * 4 + 128];
                    float4 b3 = *(const float4*)&Bs[k * BSTR + tx * 4 + 192];
                    float av;
                    #pragma unroll
                    for (int r = 0; r < 4; r++) {
                        av = (r == 0) ? a.x : (r == 1) ? a.y : (r == 2) ? a.z : a.w;
                        acc[r][0]  += av * b0.x; acc[r][1]  += av * b0.y;
                        acc[r][2]  += av * b0.z; acc[r][3]  += av * b0.w;
                        acc[r][4]  += av * b1.x; acc[r][5]  += av * b1.y;
                        acc[r][6]  += av * b1.z; acc[r][7]  += av * b1.w;
                        acc[r][8]  += av * b2.x; acc[r][9]  += av * b2.y;
                        acc[r][10] += av * b2.z; acc[r][11] += av * b2.w;
                        acc[r][12] += av * b3.x; acc[r][13] += av * b3.y;
                        acc[r][14] += av * b3.z; acc[r][15] += av * b3.w;
                    }
                }
                __syncthreads();
            }

            #pragma unroll
            for (int r = 0; r < 4; r++) {
                const int b = ty * 4 + r;
                float* row = g_xw + ((size_t)b * S_ + s) * H_;
                #pragma unroll
                for (int q = 0; q < 4; q++) {
                    float4 o = make_float4(acc[r][q * 4 + 0] + bias[q].x,
                                           acc[r][q * 4 + 1] + bias[q].y,
                                           acc[r][q * 4 + 2] + bias[q].z,
                                           acc[r][q * 4 + 3] + bias[q].w);
                    *(float4*)&row[tx * 4 + 64 * q] = o;
                }
            }
            __syncthreads();
            if (tid == 0) {
                __threadfence();
                st_release_gpu(&g_flag[s], 1);
            }
        }
        return;
    }

    // ================= CONSUMER (per-batch recurrence) =====================
    float2* u2  = (float2*)sm;
    float*  vsm = sm + (size_t)USM * H_;

    const int b = blockIdx.x;

    float uw[UREG];
    #pragma unroll
    for (int j = 0; j < UREG; j++)
        uw[j] = g_UwT[j * H_ + tid];

    for (int r2 = 0; r2 < USM / 2; r2++) {
        float a = g_UwT[(UREG + 2 * r2 + 0) * H_ + tid];
        float c = g_UwT[(UREG + 2 * r2 + 1) * H_ + tid];
        u2[r2 * H_ + tid] = make_float2(a, c);
    }
    __syncthreads();

    const float ub = Ub[tid];
    float t = 0.0f;

    const float* xwp = g_xw + (size_t)b * S_ * H_ + tid;
    float*       op  = Out  + (size_t)b * S_ * H_ + tid;

    while (ld_acquire_gpu(&g_flag[0]) == 0) { }
    float xv = __ldcs(xwp);

    for (int s = 0; s < S_; s++) {
        float v = fast_tanh(xv + t);
        float* vb = vsm + (s & 1) * H_;
        vb[tid] = v;
        __syncthreads();

        // Speculative next-step fetch: acquire flag + load xw; validate AFTER
        // the ~1500-cycle dot so neither latency is exposed.
        int   fspec = 1;
        float xn    = 0.0f;
        const float* xnp = xwp + (size_t)(s + 1) * H_;
        if (s + 1 < S_) {
            fspec = ld_acquire_gpu(&g_flag[s + 1]);
            xn    = __ldcs(xnp);
        }

        const float4* v4 = (const float4*)vb;
        float a0 = ub, a1 = 0.f, a2 = 0.f, a3 = 0.f;
        float a4 = 0.f, a5 = 0.f, a6 = 0.f, a7 = 0.f;

        float4 vA = v4[0];
        float4 vB = v4[1];

        // Register section: rows [0,192) = 48 float4 groups, pipelined
        #pragma unroll
        for (int q = 0; q < 48; q += 2) {
            float4 nA = v4[q + 2];
            float4 nB = v4[q + 3];
            const int j = 4 * q;
            a0 += uw[j + 0] * vA.x;  a1 += uw[j + 1] * vA.y;
            a2 += uw[j + 2] * vA.z;  a3 += uw[j + 3] * vA.w;
            a4 += uw[j + 4] * vB.x;  a5 += uw[j + 5] * vB.y;
            a6 += uw[j + 6] * vB.z;  a7 += uw[j + 7] * vB.w;
            vA = nA; vB = nB;
        }

        // Shared-memory section: rows [192,256) = 16 float4 groups
        const float2* up = u2 + tid;
        #pragma unroll
        for (int q = 48; q < 64; q += 2) {
            float4 nA, nB;
            if (q + 2 < 64) { nA = v4[q + 2]; nB = v4[q + 3]; }
            else            { nA = vA;        nB = vB;        }
            const int r2b = (4 * q - UREG) >> 1;
            float2 u0 = up[(r2b + 0) * H_];
            float2 u1 = up[(r2b + 1) * H_];
            float2 uu = up[(r2b + 2) * H_];
            float2 u3 = up[(r2b + 3) * H_];
            a0 += u0.x * vA.x;  a1 += u0.y * vA.y;
            a2 += u1.x * vA.z;  a3 += u1.y * vA.w;
            a4 += uu.x * vB.x;  a5 += uu.y * vB.y;
            a6 += u3.x * vB.z;  a7 += u3.y * vB.w;
            vA = nA; vB = nB;
        }

        t = ((a0 + a1) + (a2 + a3)) + ((a4 + a5) + (a6 + a7));
        __stcs(&op[(size_t)s * H_], t);

        // Validate speculation (slow path only during producer ramp)
        if (s + 1 < S_) {
            if (fspec == 0) {
                while (ld_acquire_gpu(&g_flag[s + 1]) == 0) { }
                xn = ld_cg_f(xnp);
            }
            xv = xn;
        }
    }

    Tfin[b * H_ + tid] = t;
}

// ---------------------------------------------------------------------------
// Launcher
// ---------------------------------------------------------------------------
extern "C" void kernel_launch(void* const* d_in, const int* in_sizes, int n_in,
                              void* d_out, int out_size) {
    const float* x  = (const float*)d_in[0];   // [B,S,E]
    const float* Ww = (const float*)d_in[1];   // [H,E]
    const float* Wb = (const float*)d_in[2];   // [H]
    const float* Uw = (const float*)d_in[3];   // [H,H]
    const float* Ub = (const float*)d_in[4];   // [H]

    float* out  = (float*)d_out;
    float* tfin = out;                          // [B,H]
    float* O    = out + (size_t)B_ * H_;        // [B,S,H]

    cudaFuncSetAttribute(fused, cudaFuncAttributeMaxDynamicSharedMemorySize,
                         SMEM_BYTES);

    prep<<<H_, H_>>>(Uw, Ww);
    fused<<<NCTAS, 256, SMEM_BYTES>>>(x, Wb, Ub, O, tfin);
}